// round 10
// baseline (speedup 1.0000x reference)
#include <cuda_runtime.h>
#include <cstdint>

// ---------------- problem constants ----------------
#define Hh  64
#define Ww  64
#define Cc  64
#define Uu  64
#define OHh 30
#define OWw 30
#define KDIM   1600           // 5*5*64
#define NCHUNK 50             // total K32 chunks per tile
#define HCHUNK 25             // chunks per split-K half
#define LDSS   36             // smem row stride (bank = 4r+c -> conflict-free fragments)
#define NSTG   3              // ring stages
#define OUT_ELEMS (64 * OHh * OWw * Uu)

// dynamic smem layout (floats): As[3][64][36] | Bs[3][64][36] | bias[64]
#define MAT_W   (64 * LDSS)            // 2304 floats per stage matrix
#define OFF_A(s) ((s) * MAT_W)
#define OFF_B(s) (NSTG * MAT_W + (s) * MAT_W)
#define OFF_BIAS (2 * NSTG * MAT_W)
#define SMEM_FLOATS (2 * NSTG * MAT_W + 64)
#define SMEM_BYTES  (SMEM_FLOATS * 4)   // 55552 B -> 4 CTAs/SM = 222 KB

// Raw fp32 bits into the tf32 mma (truncation-to-tf32): no cvt in mainloop.
__device__ __forceinline__ uint32_t tf32_bits(float v) { return __float_as_uint(v); }

__device__ __forceinline__ void mma_16n8k8(float c[4], const uint32_t a[4], const uint32_t b[2]) {
    asm volatile(
        "mma.sync.aligned.m16n8k8.row.col.f32.tf32.tf32.f32 "
        "{%0,%1,%2,%3}, {%4,%5,%6,%7}, {%8,%9}, {%0,%1,%2,%3};"
        : "+f"(c[0]), "+f"(c[1]), "+f"(c[2]), "+f"(c[3])
        : "r"(a[0]), "r"(a[1]), "r"(a[2]), "r"(a[3]), "r"(b[0]), "r"(b[1]));
}

__device__ __forceinline__ void cp16(uint32_t dst, const float* src) {
    asm volatile("cp.async.cg.shared.global [%0], [%1], 16;" :: "r"(dst), "l"(src));
}
// W is streaming / read-once: evict_first so it doesn't blow x out of L2.
__device__ __forceinline__ void cp16_ef(uint32_t dst, const float* src, uint64_t pol) {
    asm volatile("cp.async.cg.shared.global.L2::cache_hint [%0], [%1], 16, %2;"
                 :: "r"(dst), "l"(src), "l"(pol));
}
#define CP_COMMIT() asm volatile("cp.async.commit_group;" ::: "memory")

// ---------------- zero kernel (out is poisoned by harness) ----------------
__global__ void zero_out_kernel(float* __restrict__ out) {
    const int i = blockIdx.x * blockDim.x + threadIdx.x;
    float4 z = make_float4(0.f, 0.f, 0.f, 0.f);
    reinterpret_cast<float4*>(out)[i] = z;   // OUT_ELEMS/4 threads exactly
}

// ---------------- main kernel: split-K x2, 3-stage ring ----------------
__global__ void __launch_bounds__(128, 4)
freeconv_mma_kernel(const float* __restrict__ x, const float* __restrict__ w,
                    const float* __restrict__ bias, float* __restrict__ out) {
    extern __shared__ float sm[];

    const int tid  = threadIdx.x;
    const int wid  = tid >> 5;
    const int lane = tid & 31;
    const int g    = lane >> 2;     // 0..7
    const int t    = lane & 3;      // 0..3
    const int tile = blockIdx.x >> 1;
    const int half = blockIdx.x & 1;
    const int oh = tile / OWw, ow = tile % OWw;
    const int ih0 = oh * 2, iw0 = ow * 2;
    const int warpM = (wid >> 1) * 32;   // 0 or 32
    const int warpN = (wid & 1) * 32;    // 0 or 32
    const int cbase = half * HCHUNK;     // global chunk id base for this half

    uint64_t pol;
    asm("createpolicy.fractional.L2::evict_first.b64 %0, 1.0;" : "=l"(pol));

    if (half == 0 && tid < 64) sm[OFF_BIAS + tid] = bias[(size_t)tile * Uu + tid];

    const size_t wtile = (size_t)tile * Uu * KDIM;

    // Stage one K=32 chunk (global id c): A rows = 64 batches, B rows = 64 units.
    auto load_chunk = [&](int c, int s) {
        const int ij = c >> 1, ch = c & 1;
        const int i = ij / 5, j = ij - i * 5;
        const float* xsrc = x + (((size_t)(ih0 + i) * Ww) + (iw0 + j)) * Cc + ch * 32;
        const float* wsrc = w + wtile + (size_t)c * 32;
        const uint32_t abase = (uint32_t)__cvta_generic_to_shared(&sm[OFF_A(s)]);
        const uint32_t bbase = (uint32_t)__cvta_generic_to_shared(&sm[OFF_B(s)]);
#pragma unroll
        for (int it = 0; it < 4; it++) {
            const int idx = tid + it * 128;      // 0..511
            const int row = idx >> 3, c16 = idx & 7;
            cp16(abase + (row * LDSS) * 4 + c16 * 16,
                 xsrc + (size_t)row * (Hh * Ww * Cc) + c16 * 4);
            cp16_ef(bbase + (row * LDSS) * 4 + c16 * 16,
                    wsrc + (size_t)row * KDIM + c16 * 4, pol);
        }
    };

    float acc[2][4][4];
#pragma unroll
    for (int mt = 0; mt < 2; mt++)
#pragma unroll
        for (int nt = 0; nt < 4; nt++)
#pragma unroll
            for (int r = 0; r < 4; r++) acc[mt][nt][r] = 0.0f;

    // prologue: chunks cl=0,1 committed (depth 2 in flight)
    load_chunk(cbase + 0, 0); CP_COMMIT();
    load_chunk(cbase + 1, 1); CP_COMMIT();

    for (int cl = 0; cl < HCHUNK; cl++) {
        const int s = cl % NSTG;

        // issue next-next load first (stage held chunk cl-1, consumed & barriered)
        if (cl + 2 < HCHUNK) {
            load_chunk(cbase + cl + 2, (cl + 2) % NSTG);
            CP_COMMIT();
            asm volatile("cp.async.wait_group 2;" ::: "memory");   // cl resident
        } else if (cl + 1 < HCHUNK) {
            asm volatile("cp.async.wait_group 1;" ::: "memory");
        } else {
            asm volatile("cp.async.wait_group 0;" ::: "memory");
        }
        __syncthreads();

        const float* Ab = &sm[OFF_A(s)];
        const float* Bb = &sm[OFF_B(s)];
#pragma unroll
        for (int k8 = 0; k8 < 4; k8++) {
            const int kb = k8 * 8;
            uint32_t a[2][4], b[4][2];
#pragma unroll
            for (int mt = 0; mt < 2; mt++) {
                const int r0 = warpM + mt * 16 + g;
                a[mt][0] = tf32_bits(Ab[r0 * LDSS + kb + t]);
                a[mt][1] = tf32_bits(Ab[(r0 + 8) * LDSS + kb + t]);
                a[mt][2] = tf32_bits(Ab[r0 * LDSS + kb + t + 4]);
                a[mt][3] = tf32_bits(Ab[(r0 + 8) * LDSS + kb + t + 4]);
            }
#pragma unroll
            for (int nt = 0; nt < 4; nt++) {
                const int n0 = warpN + nt * 8 + g;
                b[nt][0] = tf32_bits(Bb[n0 * LDSS + kb + t]);
                b[nt][1] = tf32_bits(Bb[n0 * LDSS + kb + t + 4]);
            }
#pragma unroll
            for (int mt = 0; mt < 2; mt++)
#pragma unroll
                for (int nt = 0; nt < 4; nt++)
                    mma_16n8k8(acc[mt][nt], a[mt], b[nt]);
        }
        __syncthreads();
    }

    // epilogue: atomicAdd into pre-zeroed out; half 0 also adds bias
#pragma unroll
    for (int mt = 0; mt < 2; mt++) {
        const int r0 = warpM + mt * 16 + g;
#pragma unroll
        for (int nt = 0; nt < 4; nt++) {
            const int col = warpN + nt * 8 + 2 * t;
            float b0 = 0.f, b1 = 0.f;
            if (half == 0) { b0 = sm[OFF_BIAS + col]; b1 = sm[OFF_BIAS + col + 1]; }
            float* op0 = out + (((size_t)r0 * OHh + oh) * OWw + ow) * Uu + col;
            float* op1 = out + (((size_t)(r0 + 8) * OHh + oh) * OWw + ow) * Uu + col;
            atomicAdd(op0,     acc[mt][nt][0] + b0);
            atomicAdd(op0 + 1, acc[mt][nt][1] + b1);
            atomicAdd(op1,     acc[mt][nt][2] + b0);
            atomicAdd(op1 + 1, acc[mt][nt][3] + b1);
        }
    }
}

// ---------------- launch ----------------
extern "C" void kernel_launch(void* const* d_in, const int* in_sizes, int n_in,
                              void* d_out, int out_size) {
    (void)in_sizes; (void)n_in; (void)out_size;
    static bool attr_set = false;
    if (!attr_set) {
        cudaFuncSetAttribute(freeconv_mma_kernel,
                             cudaFuncAttributeMaxDynamicSharedMemorySize, SMEM_BYTES);
        attr_set = true;
    }
    const float* x = (const float*)d_in[0];
    const float* w = (const float*)d_in[1];
    const float* b = (const float*)d_in[2];
    float* o = (float*)d_out;

    zero_out_kernel<<<OUT_ELEMS / 4 / 256, 256>>>(o);
    freeconv_mma_kernel<<<OHh * OWw * 2, 128, SMEM_BYTES>>>(x, w, b, o);
}